// round 11
// baseline (speedup 1.0000x reference)
#include <cuda_runtime.h>
#include <cuda_fp16.h>
#include <cstdint>

#define N_NODES 100000
#define N_EDGES 3200000
#define N_RELS  8
#define F_DIM   64

#define SCAN_BLK 1024
#define SCAN_NBLK ((N_NODES + SCAN_BLK - 1) / SCAN_BLK)   // 98

#define EBLOCKS ((N_EDGES + 255) / 256)                   // 12500
#define WCONV_BLOCKS ((N_RELS * 64 * 64 + 255) / 256)     // 128
#define XW_BLOCKS ((N_NODES + 63) / 64)                   // 1563
#define PERM_BLOCKS ((N_NODES + 255) / 256)               // 391

// fp16 per-relation transformed features: 102.4 MB
__device__ __half g_XWh[(size_t)N_RELS * N_NODES * F_DIM];
// fp16 transposed weights: g_Wht[r][n][k]
__device__ __half g_Wht[N_RELS * F_DIM * F_DIM];
// CSR-by-dst build
__device__ int g_count[N_NODES];
__device__ int g_tmp[N_NODES];
__device__ int g_start[N_NODES];
__device__ int g_cursor[N_NODES];
__device__ int g_blocktot[SCAN_NBLK];
__device__ int g_blockoff[SCAN_NBLK];
// degree-binned node permutation (counting sort, 256 bins)
__device__ int g_dbins[256];
__device__ int g_dbincur[256];
__device__ int g_perm[N_NODES];
// packed edge records grouped by dst: lo32 = src | (rel<<17), hi32 = bits(A)
__device__ unsigned long long g_recs[N_EDGES];

// ---------------------------------------------------------------------------
// Fused: histogram over dst  +  W pre-convert/transpose (independent work)
// ---------------------------------------------------------------------------
__global__ __launch_bounds__(256) void hist_wconv_kernel(const int* __restrict__ dst,
                                                         const float* __restrict__ W) {
    int bx = blockIdx.x;
    if (bx < EBLOCKS) {
        int e = bx * 256 + threadIdx.x;
        if (e < N_EDGES) atomicAdd(&g_count[dst[e]], 1);
    } else {
        int i = (bx - EBLOCKS) * 256 + threadIdx.x;
        if (i < N_RELS * 64 * 64) {
            int r = i >> 12;
            int n = (i >> 6) & 63;
            int k = i & 63;
            g_Wht[i] = __float2half_rn(W[r * 4096 + k * 64 + n]);
        }
    }
}

// ---------------------------------------------------------------------------
// Scan (3 kernels); scan3 also builds the degree histogram
// ---------------------------------------------------------------------------
__global__ __launch_bounds__(SCAN_BLK) void scan1_kernel() {
    __shared__ int s[SCAN_BLK];
    int t = threadIdx.x;
    int i = blockIdx.x * SCAN_BLK + t;
    int v = (i < N_NODES) ? g_count[i] : 0;
    s[t] = v;
    __syncthreads();
    for (int off = 1; off < SCAN_BLK; off <<= 1) {
        int add = (t >= off) ? s[t - off] : 0;
        __syncthreads();
        s[t] += add;
        __syncthreads();
    }
    if (i < N_NODES) g_tmp[i] = s[t];
    if (t == SCAN_BLK - 1) g_blocktot[blockIdx.x] = s[t];
}

__global__ __launch_bounds__(128) void scan2_kernel() {
    __shared__ int s[128];
    int t = threadIdx.x;
    s[t] = (t < SCAN_NBLK) ? g_blocktot[t] : 0;
    __syncthreads();
    for (int off = 1; off < 128; off <<= 1) {
        int add = (t >= off) ? s[t - off] : 0;
        __syncthreads();
        s[t] += add;
        __syncthreads();
    }
    if (t < SCAN_NBLK) g_blockoff[t] = s[t] - g_blocktot[t];
}

__global__ __launch_bounds__(SCAN_BLK) void scan3_kernel() {
    int i = blockIdx.x * SCAN_BLK + threadIdx.x;
    if (i < N_NODES) {
        int ct = g_count[i];
        int st = g_tmp[i] - ct + g_blockoff[blockIdx.x];
        g_start[i] = st;
        g_cursor[i] = st;
        int b = ct < 255 ? ct : 255;
        atomicAdd(&g_dbins[b], 1);         // degree histogram
    }
}

// Exclusive scan of 256 degree bins (one block)
__global__ __launch_bounds__(256) void dscan_kernel() {
    __shared__ int s[256];
    int t = threadIdx.x;
    s[t] = g_dbins[t];
    __syncthreads();
    for (int off = 1; off < 256; off <<= 1) {
        int add = (t >= off) ? s[t - off] : 0;
        __syncthreads();
        s[t] += add;
        __syncthreads();
    }
    g_dbincur[t] = s[t] - g_dbins[t];      // exclusive offset = cursor init
}

// ---------------------------------------------------------------------------
// Fused: record scatter + XW GEMM + degree-permutation scatter
// ---------------------------------------------------------------------------
__global__ __launch_bounds__(256) void scatter_xw_kernel(const float* __restrict__ A,
                                                         const int* __restrict__ src,
                                                         const int* __restrict__ dst,
                                                         const int* __restrict__ etype,
                                                         const float* __restrict__ X,
                                                         __half* __restrict__ XWh) {
    __shared__ __half Xh[64][72];
    __shared__ __half Wt[64][72];

    int bx = blockIdx.x;
    if (bx >= XW_BLOCKS + EBLOCKS) {
        // ---- degree-permutation scatter path ----
        int n = (bx - XW_BLOCKS - EBLOCKS) * 256 + threadIdx.x;
        if (n < N_NODES) {
            int ct = g_count[n];
            int b = ct < 255 ? ct : 255;
            int pos = atomicAdd(&g_dbincur[b], 1);
            g_perm[pos] = n;
        }
        return;
    }
    if (bx >= XW_BLOCKS) {
        // ---- record scatter path ----
        int e = (bx - XW_BLOCKS) * 256 + threadIdx.x;
        if (e >= N_EDGES) return;
        int d = dst[e];
        int p = atomicAdd(&g_cursor[d], 1);
        unsigned key = (unsigned)src[e] | ((unsigned)etype[e] << 17);
        unsigned long long rec = (unsigned long long)key |
                                 ((unsigned long long)__float_as_uint(A[e]) << 32);
        g_recs[p] = rec;
        return;
    }

    // ---- xw path ----
    const int n0blk = bx * 64;

    for (int i = threadIdx.x; i < 64 * 32; i += 256) {
        int row = i >> 5, cp = i & 31;
        int n = n0blk + row;
        float2 v = (n < N_NODES)
            ? *reinterpret_cast<const float2*>(X + (size_t)n * 64 + cp * 2)
            : make_float2(0.0f, 0.0f);
        *reinterpret_cast<__half2*>(&Xh[row][cp * 2]) = __floats2half2_rn(v.x, v.y);
    }

    const int warp = threadIdx.x >> 5;
    const int lane = threadIdx.x & 31;
    const int g = lane >> 2;
    const int t = lane & 3;
    const int r0 = (warp & 3) * 16;
    const int ch = (warp >> 2) * 32;

    for (int r = 0; r < N_RELS; r++) {
        __syncthreads();
        for (int i = threadIdx.x; i < 64 * 32; i += 256) {
            int n = i >> 5, kp = i & 31;
            *reinterpret_cast<__half2*>(&Wt[n][kp * 2]) =
                *reinterpret_cast<const __half2*>(&g_Wht[r * 4096 + n * 64 + kp * 2]);
        }
        __syncthreads();

        float acc[4][4];
#pragma unroll
        for (int j = 0; j < 4; j++)
#pragma unroll
            for (int c = 0; c < 4; c++) acc[j][c] = 0.0f;

#pragma unroll
        for (int kk = 0; kk < 4; kk++) {
            const int k0 = kk * 16;
            uint32_t a0 = *reinterpret_cast<const uint32_t*>(&Xh[r0 + g    ][k0 + 2 * t    ]);
            uint32_t a1 = *reinterpret_cast<const uint32_t*>(&Xh[r0 + g + 8][k0 + 2 * t    ]);
            uint32_t a2 = *reinterpret_cast<const uint32_t*>(&Xh[r0 + g    ][k0 + 2 * t + 8]);
            uint32_t a3 = *reinterpret_cast<const uint32_t*>(&Xh[r0 + g + 8][k0 + 2 * t + 8]);
#pragma unroll
            for (int j = 0; j < 4; j++) {
                const int n0 = ch + j * 8;
                uint32_t b0 = *reinterpret_cast<const uint32_t*>(&Wt[n0 + g][k0 + 2 * t    ]);
                uint32_t b1 = *reinterpret_cast<const uint32_t*>(&Wt[n0 + g][k0 + 2 * t + 8]);
                asm volatile(
                    "mma.sync.aligned.m16n8k16.row.col.f32.f16.f16.f32 "
                    "{%0,%1,%2,%3}, {%4,%5,%6,%7}, {%8,%9}, {%0,%1,%2,%3};"
                    : "+f"(acc[j][0]), "+f"(acc[j][1]), "+f"(acc[j][2]), "+f"(acc[j][3])
                    : "r"(a0), "r"(a1), "r"(a2), "r"(a3), "r"(b0), "r"(b1));
            }
        }

        __half* base = XWh + (size_t)r * N_NODES * 64;
#pragma unroll
        for (int j = 0; j < 4; j++) {
            const int col = ch + j * 8 + 2 * t;
            const int row_a = n0blk + r0 + g;
            const int row_b = row_a + 8;
            __half2 lo = __floats2half2_rn(acc[j][0], acc[j][1]);
            __half2 hi = __floats2half2_rn(acc[j][2], acc[j][3]);
            if (row_a < N_NODES)
                *reinterpret_cast<__half2*>(base + (size_t)row_a * 64 + col) = lo;
            if (row_b < N_NODES)
                *reinterpret_cast<__half2*>(base + (size_t)row_b * 64 + col) = hi;
        }
    }
}

// ---------------------------------------------------------------------------
// Gather: warp-per-node in degree-sorted order (co-resident warps have equal
// trip counts). Hot loop identical to R8 winner: branch-free, 8-deep chains.
// ---------------------------------------------------------------------------
__global__ __launch_bounds__(256) void gather_kernel(const __half* __restrict__ XWh,
                                                     float* __restrict__ Y) {
    const int wi = blockIdx.x * 8 + (threadIdx.x >> 5);
    if (wi >= N_NODES) return;
    const int node = g_perm[wi];
    const int lane = threadIdx.x & 31;

    const int s = g_start[node];
    const int end = s + g_count[node];

    float acc0 = 0.0f, acc1 = 0.0f;

    int i = s;
    for (; i + 8 <= end; i += 8) {
        unsigned long long rr[8];
#pragma unroll
        for (int q = 0; q < 8; q++) rr[q] = g_recs[i + q];

        float2 f[8];
        float a[8];
#pragma unroll
        for (int q = 0; q < 8; q++) {
            unsigned k = (unsigned)rr[q];
            a[q] = __uint_as_float((unsigned)(rr[q] >> 32));
            size_t row = (size_t)(k >> 17) * N_NODES + (k & 0x1FFFF);
            __half2 h = *(reinterpret_cast<const __half2*>(XWh + row * 64) + lane);
            f[q] = __half22float2(h);
        }
#pragma unroll
        for (int q = 0; q < 8; q++) {
            acc0 = fmaf(f[q].x, a[q], acc0);
            acc1 = fmaf(f[q].y, a[q], acc1);
        }
    }
    for (; i < end; i++) {
        unsigned long long r0 = g_recs[i];
        unsigned k0 = (unsigned)r0;
        float a0 = __uint_as_float((unsigned)(r0 >> 32));
        size_t row0 = (size_t)(k0 >> 17) * N_NODES + (k0 & 0x1FFFF);
        __half2 h0 = *(reinterpret_cast<const __half2*>(XWh + row0 * 64) + lane);
        float2 f0 = __half22float2(h0);
        acc0 = fmaf(f0.x, a0, acc0);
        acc1 = fmaf(f0.y, a0, acc1);
    }

    *reinterpret_cast<float2*>(Y + (size_t)node * 64 + 2 * lane) =
        make_float2(acc0, acc1);
}

// ---------------------------------------------------------------------------
extern "C" void kernel_launch(void* const* d_in, const int* in_sizes, int n_in,
                              void* d_out, int out_size) {
    const float* X     = (const float*)d_in[0];
    const float* W     = (const float*)d_in[1];
    const float* A     = (const float*)d_in[2];
    const int*   src   = (const int*)d_in[3];
    const int*   dst   = (const int*)d_in[4];
    const int*   etype = (const int*)d_in[5];
    float* Y = (float*)d_out;

    __half* XWh = nullptr;
    cudaGetSymbolAddress((void**)&XWh, g_XWh);
    void* countp = nullptr;
    cudaGetSymbolAddress(&countp, g_count);
    void* dbinp = nullptr;
    cudaGetSymbolAddress(&dbinp, g_dbins);

    cudaMemsetAsync(countp, 0, N_NODES * sizeof(int), 0);
    cudaMemsetAsync(dbinp, 0, 256 * sizeof(int), 0);

    hist_wconv_kernel<<<EBLOCKS + WCONV_BLOCKS, 256>>>(dst, W);
    scan1_kernel<<<SCAN_NBLK, SCAN_BLK>>>();
    scan2_kernel<<<1, 128>>>();
    scan3_kernel<<<SCAN_NBLK, SCAN_BLK>>>();
    dscan_kernel<<<1, 256>>>();

    // record scatter + XW GEMM + degree-permutation scatter (independent)
    scatter_xw_kernel<<<XW_BLOCKS + EBLOCKS + PERM_BLOCKS, 256>>>(
        A, src, dst, etype, X, XWh);

    // degree-balanced warp-per-node gather
    gather_kernel<<<(N_NODES + 7) / 8, 256>>>(XWh, Y);
}

// round 12
// speedup vs baseline: 1.2568x; 1.2568x over previous
#include <cuda_runtime.h>
#include <cuda_fp16.h>
#include <cstdint>

#define N_NODES 100000
#define N_EDGES 3200000
#define N_RELS  8
#define F_DIM   64

#define SCAN_BLK 1024
#define SCAN_NBLK ((N_NODES + SCAN_BLK - 1) / SCAN_BLK)   // 98

#define EBLOCKS ((N_EDGES + 255) / 256)                   // 12500
#define WCONV_BLOCKS ((N_RELS * 64 * 64 + 255) / 256)     // 128
#define XW_BLOCKS ((N_NODES + 63) / 64)                   // 1563

// fp16 per-relation transformed features: 102.4 MB
__device__ __half g_XWh[(size_t)N_RELS * N_NODES * F_DIM];
// fp16 transposed weights: g_Wht[r][n][k]
__device__ __half g_Wht[N_RELS * F_DIM * F_DIM];
// CSR-by-dst build
__device__ int g_count[N_NODES];
__device__ int g_tmp[N_NODES];
__device__ int g_start[N_NODES];
__device__ int g_cursor[N_NODES];
__device__ int g_blocktot[SCAN_NBLK];
__device__ int g_blockoff[SCAN_NBLK];
// packed edge records grouped by dst: lo32 = src | (rel<<17), hi32 = bits(A)
// 16B-aligned so pairs can be read with LDG.128
__device__ __align__(16) unsigned long long g_recs[N_EDGES];

// ---------------------------------------------------------------------------
// Fused: histogram over dst  +  W pre-convert/transpose (independent work)
// ---------------------------------------------------------------------------
__global__ __launch_bounds__(256) void hist_wconv_kernel(const int* __restrict__ dst,
                                                         const float* __restrict__ W) {
    int bx = blockIdx.x;
    if (bx < EBLOCKS) {
        int e = bx * 256 + threadIdx.x;
        if (e < N_EDGES) atomicAdd(&g_count[dst[e]], 1);
    } else {
        int i = (bx - EBLOCKS) * 256 + threadIdx.x;
        if (i < N_RELS * 64 * 64) {
            int r = i >> 12;
            int n = (i >> 6) & 63;
            int k = i & 63;
            g_Wht[i] = __float2half_rn(W[r * 4096 + k * 64 + n]);
        }
    }
}

// ---------------------------------------------------------------------------
// Scan (3 kernels)
// ---------------------------------------------------------------------------
__global__ __launch_bounds__(SCAN_BLK) void scan1_kernel() {
    __shared__ int s[SCAN_BLK];
    int t = threadIdx.x;
    int i = blockIdx.x * SCAN_BLK + t;
    int v = (i < N_NODES) ? g_count[i] : 0;
    s[t] = v;
    __syncthreads();
    for (int off = 1; off < SCAN_BLK; off <<= 1) {
        int add = (t >= off) ? s[t - off] : 0;
        __syncthreads();
        s[t] += add;
        __syncthreads();
    }
    if (i < N_NODES) g_tmp[i] = s[t];
    if (t == SCAN_BLK - 1) g_blocktot[blockIdx.x] = s[t];
}

__global__ __launch_bounds__(128) void scan2_kernel() {
    __shared__ int s[128];
    int t = threadIdx.x;
    s[t] = (t < SCAN_NBLK) ? g_blocktot[t] : 0;
    __syncthreads();
    for (int off = 1; off < 128; off <<= 1) {
        int add = (t >= off) ? s[t - off] : 0;
        __syncthreads();
        s[t] += add;
        __syncthreads();
    }
    if (t < SCAN_NBLK) g_blockoff[t] = s[t] - g_blocktot[t];
}

__global__ __launch_bounds__(SCAN_BLK) void scan3_kernel() {
    int i = blockIdx.x * SCAN_BLK + threadIdx.x;
    if (i < N_NODES) {
        int st = g_tmp[i] - g_count[i] + g_blockoff[blockIdx.x];
        g_start[i] = st;
        g_cursor[i] = st;
    }
}

// ---------------------------------------------------------------------------
// Fused: record scatter  +  XW GEMM (independent work, co-resident overlap)
// ---------------------------------------------------------------------------
__global__ __launch_bounds__(256) void scatter_xw_kernel(const float* __restrict__ A,
                                                         const int* __restrict__ src,
                                                         const int* __restrict__ dst,
                                                         const int* __restrict__ etype,
                                                         const float* __restrict__ X,
                                                         __half* __restrict__ XWh) {
    __shared__ __half Xh[64][72];
    __shared__ __half Wt[64][72];

    int bx = blockIdx.x;
    if (bx >= XW_BLOCKS) {
        // ---- scatter path ----
        int e = (bx - XW_BLOCKS) * 256 + threadIdx.x;
        if (e >= N_EDGES) return;
        int d = dst[e];
        int p = atomicAdd(&g_cursor[d], 1);
        unsigned key = (unsigned)src[e] | ((unsigned)etype[e] << 17);
        unsigned long long rec = (unsigned long long)key |
                                 ((unsigned long long)__float_as_uint(A[e]) << 32);
        g_recs[p] = rec;
        return;
    }

    // ---- xw path ----
    const int n0blk = bx * 64;

    for (int i = threadIdx.x; i < 64 * 32; i += 256) {
        int row = i >> 5, cp = i & 31;
        int n = n0blk + row;
        float2 v = (n < N_NODES)
            ? *reinterpret_cast<const float2*>(X + (size_t)n * 64 + cp * 2)
            : make_float2(0.0f, 0.0f);
        *reinterpret_cast<__half2*>(&Xh[row][cp * 2]) = __floats2half2_rn(v.x, v.y);
    }

    const int warp = threadIdx.x >> 5;
    const int lane = threadIdx.x & 31;
    const int g = lane >> 2;
    const int t = lane & 3;
    const int r0 = (warp & 3) * 16;
    const int ch = (warp >> 2) * 32;

    for (int r = 0; r < N_RELS; r++) {
        __syncthreads();
        for (int i = threadIdx.x; i < 64 * 32; i += 256) {
            int n = i >> 5, kp = i & 31;
            *reinterpret_cast<__half2*>(&Wt[n][kp * 2]) =
                *reinterpret_cast<const __half2*>(&g_Wht[r * 4096 + n * 64 + kp * 2]);
        }
        __syncthreads();

        float acc[4][4];
#pragma unroll
        for (int j = 0; j < 4; j++)
#pragma unroll
            for (int c = 0; c < 4; c++) acc[j][c] = 0.0f;

#pragma unroll
        for (int kk = 0; kk < 4; kk++) {
            const int k0 = kk * 16;
            uint32_t a0 = *reinterpret_cast<const uint32_t*>(&Xh[r0 + g    ][k0 + 2 * t    ]);
            uint32_t a1 = *reinterpret_cast<const uint32_t*>(&Xh[r0 + g + 8][k0 + 2 * t    ]);
            uint32_t a2 = *reinterpret_cast<const uint32_t*>(&Xh[r0 + g    ][k0 + 2 * t + 8]);
            uint32_t a3 = *reinterpret_cast<const uint32_t*>(&Xh[r0 + g + 8][k0 + 2 * t + 8]);
#pragma unroll
            for (int j = 0; j < 4; j++) {
                const int n0 = ch + j * 8;
                uint32_t b0 = *reinterpret_cast<const uint32_t*>(&Wt[n0 + g][k0 + 2 * t    ]);
                uint32_t b1 = *reinterpret_cast<const uint32_t*>(&Wt[n0 + g][k0 + 2 * t + 8]);
                asm volatile(
                    "mma.sync.aligned.m16n8k16.row.col.f32.f16.f16.f32 "
                    "{%0,%1,%2,%3}, {%4,%5,%6,%7}, {%8,%9}, {%0,%1,%2,%3};"
                    : "+f"(acc[j][0]), "+f"(acc[j][1]), "+f"(acc[j][2]), "+f"(acc[j][3])
                    : "r"(a0), "r"(a1), "r"(a2), "r"(a3), "r"(b0), "r"(b1));
            }
        }

        __half* base = XWh + (size_t)r * N_NODES * 64;
#pragma unroll
        for (int j = 0; j < 4; j++) {
            const int col = ch + j * 8 + 2 * t;
            const int row_a = n0blk + r0 + g;
            const int row_b = row_a + 8;
            __half2 lo = __floats2half2_rn(acc[j][0], acc[j][1]);
            __half2 hi = __floats2half2_rn(acc[j][2], acc[j][3]);
            if (row_a < N_NODES)
                *reinterpret_cast<__half2*>(base + (size_t)row_a * 64 + col) = lo;
            if (row_b < N_NODES)
                *reinterpret_cast<__half2*>(base + (size_t)row_b * 64 + col) = hi;
        }
    }
}

// ---------------------------------------------------------------------------
// Gather: one warp per dst node, 8-edge unroll. Record loads paired into
// LDG.128 (uint4 = 2 records); odd row start peeled outside the hot loop.
// ---------------------------------------------------------------------------
__global__ __launch_bounds__(256) void gather_kernel(const __half* __restrict__ XWh,
                                                     float* __restrict__ Y) {
    const int node = blockIdx.x * 8 + (threadIdx.x >> 5);
    if (node >= N_NODES) return;
    const int lane = threadIdx.x & 31;

    const int s = g_start[node];
    const int end = s + g_count[node];

    float acc0 = 0.0f, acc1 = 0.0f;

    int i = s;
    // Peel to 16B alignment
    if ((i & 1) && i < end) {
        unsigned long long r0 = g_recs[i];
        unsigned k0 = (unsigned)r0;
        float a0 = __uint_as_float((unsigned)(r0 >> 32));
        size_t row0 = (size_t)(k0 >> 17) * N_NODES + (k0 & 0x1FFFF);
        __half2 h0 = *(reinterpret_cast<const __half2*>(XWh + row0 * 64) + lane);
        float2 f0 = __half22float2(h0);
        acc0 = fmaf(f0.x, a0, acc0);
        acc1 = fmaf(f0.y, a0, acc1);
        i++;
    }

    for (; i + 8 <= end; i += 8) {
        uint4 rp[4];
#pragma unroll
        for (int q = 0; q < 4; q++)
            rp[q] = *reinterpret_cast<const uint4*>(g_recs + i + 2 * q);

        float2 f[8];
        float a[8];
#pragma unroll
        for (int q = 0; q < 4; q++) {
            unsigned ka = rp[q].x;             // record 2q
            unsigned kb = rp[q].z;             // record 2q+1
            a[2 * q]     = __uint_as_float(rp[q].y);
            a[2 * q + 1] = __uint_as_float(rp[q].w);
            size_t rowa = (size_t)(ka >> 17) * N_NODES + (ka & 0x1FFFF);
            size_t rowb = (size_t)(kb >> 17) * N_NODES + (kb & 0x1FFFF);
            __half2 ha = *(reinterpret_cast<const __half2*>(XWh + rowa * 64) + lane);
            __half2 hb = *(reinterpret_cast<const __half2*>(XWh + rowb * 64) + lane);
            f[2 * q]     = __half22float2(ha);
            f[2 * q + 1] = __half22float2(hb);
        }
#pragma unroll
        for (int q = 0; q < 8; q++) {
            acc0 = fmaf(f[q].x, a[q], acc0);
            acc1 = fmaf(f[q].y, a[q], acc1);
        }
    }
    for (; i < end; i++) {
        unsigned long long r0 = g_recs[i];
        unsigned k0 = (unsigned)r0;
        float a0 = __uint_as_float((unsigned)(r0 >> 32));
        size_t row0 = (size_t)(k0 >> 17) * N_NODES + (k0 & 0x1FFFF);
        __half2 h0 = *(reinterpret_cast<const __half2*>(XWh + row0 * 64) + lane);
        float2 f0 = __half22float2(h0);
        acc0 = fmaf(f0.x, a0, acc0);
        acc1 = fmaf(f0.y, a0, acc1);
    }

    *reinterpret_cast<float2*>(Y + (size_t)node * 64 + 2 * lane) =
        make_float2(acc0, acc1);
}

// ---------------------------------------------------------------------------
extern "C" void kernel_launch(void* const* d_in, const int* in_sizes, int n_in,
                              void* d_out, int out_size) {
    const float* X     = (const float*)d_in[0];
    const float* W     = (const float*)d_in[1];
    const float* A     = (const float*)d_in[2];
    const int*   src   = (const int*)d_in[3];
    const int*   dst   = (const int*)d_in[4];
    const int*   etype = (const int*)d_in[5];
    float* Y = (float*)d_out;

    __half* XWh = nullptr;
    cudaGetSymbolAddress((void**)&XWh, g_XWh);
    void* countp = nullptr;
    cudaGetSymbolAddress(&countp, g_count);

    cudaMemsetAsync(countp, 0, N_NODES * sizeof(int), 0);

    hist_wconv_kernel<<<EBLOCKS + WCONV_BLOCKS, 256>>>(dst, W);
    scan1_kernel<<<SCAN_NBLK, SCAN_BLK>>>();
    scan2_kernel<<<1, 128>>>();
    scan3_kernel<<<SCAN_NBLK, SCAN_BLK>>>();

    // scatter + XW GEMM co-resident (independent work)
    scatter_xw_kernel<<<XW_BLOCKS + EBLOCKS, 256>>>(A, src, dst, etype, X, XWh);

    // warp-per-node gather (writes every Y element; no memset needed)
    gather_kernel<<<(N_NODES + 7) / 8, 256>>>(XWh, Y);
}